// round 13
// baseline (speedup 1.0000x reference)
#include <cuda_runtime.h>
#include <cuda_fp16.h>
#include <cstdint>

#define NN    20000
#define DD    32
#define HH    64
#define G4    256
#define MT    32
#define NBLK_LSTM (NN / MT)   // 625

// ---------------- scratch ----------------
__device__ int    g_nbr_sorted[NN * DD];
__device__ __half g_x0[(size_t)NN * 16];     // layer-0 features padded to 16 fp16
__device__ __half g_h16a[(size_t)NN * HH];   // layer outputs (fp16), ping
__device__ __half g_h16b[(size_t)NN * HH];   // pong

// ---------------- helpers ----------------
__device__ __forceinline__ uint32_t pack2(float a, float b) {
    __half2 h = __floats2half2_rn(a, b);
    return *reinterpret_cast<uint32_t*>(&h);
}
__device__ __forceinline__ __half2 tanh_h2(__half2 x) {
    uint32_t xi = *reinterpret_cast<uint32_t*>(&x);
    uint32_t yi;
    asm("tanh.approx.f16x2 %0, %1;" : "=r"(yi) : "r"(xi));
    return *reinterpret_cast<__half2*>(&yi);
}
__device__ __forceinline__ __half2 sig_h2(__half2 x) {
    const __half2 h = __float2half2_rn(0.5f);
    return __hfma2(tanh_h2(__hmul2(x, h)), h, h);
}
__device__ __forceinline__ void cp_async16(uint32_t dst_smem, const void* src) {
    asm volatile("cp.async.ca.shared.global [%0], [%1], 16;" :: "r"(dst_smem), "l"(src));
}
#define LDM4(r, a) \
    asm volatile("ldmatrix.sync.aligned.m8n8.x4.shared.b16 {%0,%1,%2,%3}, [%4];" \
                 : "=r"((r)[0]), "=r"((r)[1]), "=r"((r)[2]), "=r"((r)[3]) : "r"(a))
#define LDM2(r0, r1, a) \
    asm volatile("ldmatrix.sync.aligned.m8n8.x2.shared.b16 {%0,%1}, [%2];" \
                 : "=r"(r0), "=r"(r1) : "r"(a))
#define MMA(d, a, b0, b1) \
    asm volatile("mma.sync.aligned.m16n8k16.row.col.f32.f16.f16.f32 " \
                 "{%0,%1,%2,%3}, {%4,%5,%6,%7}, {%8,%9}, {%0,%1,%2,%3};" \
                 : "+f"((d)[0]), "+f"((d)[1]), "+f"((d)[2]), "+f"((d)[3]) \
                 : "r"((a)[0]), "r"((a)[1]), "r"((a)[2]), "r"((a)[3]), "r"(b0), "r"(b1))

// ---------------- 1) sort neighbors ----------------
__global__ void sort_nbr_kernel(const int* __restrict__ nbr) {
    int gtid = blockIdx.x * blockDim.x + threadIdx.x;
    int node = gtid >> 5;
    int lane = gtid & 31;
    if (node >= NN) return;
    int v = nbr[node * DD + lane];
#pragma unroll
    for (int k = 2; k <= 32; k <<= 1) {
#pragma unroll
        for (int j = k >> 1; j > 0; j >>= 1) {
            int p = __shfl_xor_sync(0xffffffffu, v, j);
            bool keepMin = (((lane & j) == 0) == ((lane & k) == 0));
            int mn = min(v, p), mx = max(v, p);
            v = keepMin ? mn : mx;
        }
    }
    g_nbr_sorted[node * DD + lane] = v;
}

// ---------------- 1b) prep layer-0 x: [N,3] f32 -> [N,16] fp16 padded ----------------
__global__ void prep_x0_kernel(const float* __restrict__ nf) {
    int i = blockIdx.x * 256 + threadIdx.x;
    if (i >= NN * 16) return;
    int n = i >> 4, k = i & 15;
    g_x0[i] = __float2half(k < 3 ? nf[n * 3 + k] : 0.0f);
}

// ---------------- 2) fused LSTM (x-gather) + combine (+ out) ----------------
// In-loop: gates = bias + x_t@W_ih^T + h@W_hh^T (all HMMA fp32-acc).
// x_t rows gathered as fp16 (XK*2 B/row) via cp.async, double-buffered.
// W_hh in registers (B-frags); W_ih in smem (n-major, ldmatrix.x2 per step).
// f16x2 activations, fp32 cell state.
// Epilogue: comb = relu([x|agg]@Wl^T+bl) -> h16out (fp16); LAST: out = comb.Wo+bo.
// XK = padded x width (16/64), XKG = true x width (3/64).

template <int XK, int XKG, bool LAST>
__global__ __launch_bounds__(256, 2) void lstm_fused_kernel(
    const float* __restrict__ W_hh,
    const float* __restrict__ W_ih,
    const float* __restrict__ b_ih,
    const float* __restrict__ b_hh,
    const __half* __restrict__ xg,      // gather source ([N, XK] fp16)
    const __half* __restrict__ xc16,    // combine-x source (layers 1,2)
    const float*  __restrict__ xcf32,   // combine-x source (layer 0, width 3)
    const float*  __restrict__ Wl,
    const float*  __restrict__ bl,
    const float*  __restrict__ Wo,
    const float*  __restrict__ bo,
    __half* __restrict__ h16out,
    float* __restrict__ outp)
{
    extern __shared__ char dsm[];
    constexpr int XSTB    = MT * XK * 2;          // one x stage buffer
    constexpr int HB0     = 2 * XSTB;             // 2 x 4KB h buffers
    constexpr int WPITCH  = XK + 8;               // W_ih row pitch (halves)
    constexpr int WIH0    = HB0 + 8192;
    constexpr int KD2     = XK + 64;
    constexpr int WLPITCH = KD2 + 8;
    constexpr int WLOFF   = WIH0 + 256 * WPITCH * 2;
    constexpr int XPITCH  = XK + 8;
    constexpr int XSOFF   = WLOFF + 64 * WLPITCH * 2;
    constexpr int IDXOFF  = XSOFF + MT * XPITCH * 2;
    constexpr int KKX     = XK / 16;
    constexpr int KKC     = KD2 / 16;
    constexpr int XMASK   = (XK == 64) ? 7 : 1;

    const int tid  = threadIdx.x;
    const int w    = tid >> 5;
    const int lane = tid & 31;
    const int grp  = lane >> 2;
    const int tig  = lane & 3;
    const int sub  = lane >> 3;
    const int l7   = lane & 7;
    const int base = blockIdx.x * MT;
    const int col0 = 8 * w + tig * 2;

    const uint32_t sm32 = (uint32_t)__cvta_generic_to_shared(dsm);
    int* idx_smp = reinterpret_cast<int*>(dsm + IDXOFF);

    // ---- W_hh -> B fragments (resident in regs) ----
    uint32_t Bhh[4][4][2];
#pragma unroll
    for (int g = 0; g < 4; g++) {
        const float* row = W_hh + (size_t)(64 * g + 8 * w + grp) * HH;
#pragma unroll
        for (int kk = 0; kk < 4; kk++) {
            const float* rk = row + kk * 16 + tig * 2;
            Bhh[g][kk][0] = pack2(__ldg(rk),     __ldg(rk + 1));
            Bhh[g][kk][1] = pack2(__ldg(rk + 8), __ldg(rk + 9));
        }
    }
    // ---- bias regs ----
    float bias[4][2];
#pragma unroll
    for (int g = 0; g < 4; g++) {
#pragma unroll
        for (int e = 0; e < 2; e++) {
            int c = 64 * g + col0 + e;
            bias[g][e] = __ldg(&b_ih[c]) + __ldg(&b_hh[c]);
        }
    }

    // ---- W_ih -> smem (n-major [256][WPITCH] fp16, zero-padded) ----
    {
        __half* wsm = reinterpret_cast<__half*>(dsm + WIH0);
        for (int e = tid; e < 256 * XK; e += 256) {
            int n = e / XK, k = e - n * XK;
            float v = (k < XKG) ? __ldg(&W_ih[n * XKG + k]) : 0.0f;
            wsm[n * WPITCH + k] = __float2half(v);
        }
    }
    // ---- Wl -> smem fp16 (padded-K remap) ----
    {
        __half* wsm = reinterpret_cast<__half*>(dsm + WLOFF);
        for (int e = tid; e < 64 * KD2; e += 256) {
            int n = e / KD2, k = e - n * KD2;
            float v;
            if (k < XK) v = (k < XKG) ? __ldg(&Wl[n * (XKG + 64) + k]) : 0.0f;
            else        v = __ldg(&Wl[n * (XKG + 64) + XKG + (k - XK)]);
            wsm[n * WLPITCH + k] = __float2half(v);
        }
    }
    // ---- combine-x -> smem fp16 ----
    {
        __half* xsm = reinterpret_cast<__half*>(dsm + XSOFF);
        for (int e = tid; e < MT * XK; e += 256) {
            int r = e / XK, k = e - r * XK;
            __half v;
            if (XKG == 3) v = __float2half(k < 3 ? __ldg(&xcf32[(base + r) * 3 + k]) : 0.0f);
            else          v = xc16[(size_t)(base + r) * HH + k];
            xsm[r * XPITCH + k] = v;
        }
    }
    // ---- indices -> smem ----
    for (int e = tid; e < MT * DD; e += 256)
        idx_smp[e] = g_nbr_sorted[base * DD + e];

    // ---- ldmatrix addrs: h (128B rows, xor-swizzled) ----
    uint32_t lmh[2][4];
#pragma unroll
    for (int m = 0; m < 2; m++)
#pragma unroll
        for (int kk = 0; kk < 4; kk++) {
            int rr   = m * 16 + l7 + (sub & 1) * 8;
            int gcol = kk * 2 + (sub >> 1);
            lmh[m][kk] = sm32 + (uint32_t)(HB0 + rr * 128 + ((gcol ^ (rr & 7)) << 4));
        }
    // ---- ldmatrix addrs: x stage (XK*2-B rows) ----
    uint32_t lmx[2][KKX];
#pragma unroll
    for (int m = 0; m < 2; m++)
#pragma unroll
        for (int kk = 0; kk < KKX; kk++) {
            int rr   = m * 16 + l7 + (sub & 1) * 8;
            int gcol = kk * 2 + (sub >> 1);
            lmx[m][kk] = sm32 + (uint32_t)(rr * (XK * 2) + ((gcol ^ (rr & XMASK)) << 4));
        }
    // ---- W_ih ldmatrix base ----
    const uint32_t lmw = sm32 + (uint32_t)(WIH0 +
                         ((8 * w + l7) * WPITCH + ((lane >> 3) & 1) * 8) * 2);
    // ---- h store offsets ----
    uint32_t sth[4];
    {
        int pc = ((w ^ grp) << 3) + tig * 2;
#pragma unroll
        for (int j = 0; j < 4; j++) {
            int r = (j >> 1) * 16 + (j & 1) * 8 + grp;
            sth[j] = (uint32_t)(HB0 + r * 128 + pc * 2);
        }
    }

    // ---- cp.async mapping ----
    const int xr = (XK == 64) ? (tid >> 3) : (tid >> 1);
    const int xc = (XK == 64) ? (tid & 7)  : (tid & 1);
    const bool xact = (XK == 64) ? true : (tid < 64);
    const uint32_t xdst0 = sm32 + (uint32_t)(xr * (XK * 2) + ((xc ^ (xr & XMASK)) << 4));

    // ---- zero h buffers ----
    for (int e = tid; e < 2 * MT * HH / 2; e += 256)
        reinterpret_cast<uint32_t*>(dsm + HB0)[e] = 0u;

    // ---- preload stage(0) ----
    if (xact) {
        int idx = __ldg(&g_nbr_sorted[(base + xr) * DD + 0]);
        cp_async16(xdst0, xg + (size_t)idx * XK + xc * 8);
    }
    asm volatile("cp.async.commit_group;");

    float cst[2][4] = {{0.f,0.f,0.f,0.f},{0.f,0.f,0.f,0.f}};

#pragma unroll 1
    for (int t = 0; t < DD; t++) {
        const uint32_t xrb = (uint32_t)((t & 1) * XSTB);
        const uint32_t hrb = (uint32_t)(((t & 1) ^ 1) * 4096);
        const uint32_t hwb = (uint32_t)((t & 1) * 4096);

        asm volatile("cp.async.wait_group 0;" ::: "memory");
        __syncthreads();   // stage(t), h(t-1), prologue smem visible

        if (t < DD - 1 && xact) {
            int idx = idx_smp[xr * DD + (t + 1)];
            cp_async16(xdst0 + ((t + 1) & 1) * XSTB,
                       xg + (size_t)idx * XK + xc * 8);
        }
        asm volatile("cp.async.commit_group;");

        // ---- gate init from bias ----
        float cur[2][4][4];
#pragma unroll
        for (int m = 0; m < 2; m++)
#pragma unroll
            for (int g = 0; g < 4; g++) {
                cur[m][g][0] = bias[g][0]; cur[m][g][1] = bias[g][1];
                cur[m][g][2] = bias[g][0]; cur[m][g][3] = bias[g][1];
            }

        // ---- x-part: gates += x_t @ W_ih^T ----
#pragma unroll
        for (int kk = 0; kk < KKX; kk++) {
            uint32_t A0[4], A1[4];
            LDM4(A0, lmx[0][kk] + xrb);
            LDM4(A1, lmx[1][kk] + xrb);
#pragma unroll
            for (int g = 0; g < 4; g++) {
                uint32_t B0, B1;
                LDM2(B0, B1, lmw + (uint32_t)((64 * g * WPITCH + kk * 16) * 2));
                MMA(cur[0][g], A0, B0, B1);
                MMA(cur[1][g], A1, B0, B1);
            }
        }
        // ---- h-part: gates += h(t-1) @ W_hh^T ----
#pragma unroll
        for (int kk = 0; kk < 4; kk++) {
            uint32_t A0[4], A1[4];
            LDM4(A0, lmh[0][kk] + hrb);
            LDM4(A1, lmh[1][kk] + hrb);
#pragma unroll
            for (int g = 0; g < 4; g++) {
                MMA(cur[0][g], A0, Bhh[g][kk][0], Bhh[g][kk][1]);
                MMA(cur[1][g], A1, Bhh[g][kk][0], Bhh[g][kk][1]);
            }
        }

        // ---- activations (f16x2) + cell update (fp32 c) ----
        uint32_t hst[2][2];
#pragma unroll
        for (int m = 0; m < 2; m++)
#pragma unroll
            for (int p = 0; p < 2; p++) {
                __half2 gi = __floats2half2_rn(cur[m][0][2*p], cur[m][0][2*p+1]);
                __half2 gf = __floats2half2_rn(cur[m][1][2*p], cur[m][1][2*p+1]);
                __half2 gg = __floats2half2_rn(cur[m][2][2*p], cur[m][2][2*p+1]);
                __half2 go = __floats2half2_rn(cur[m][3][2*p], cur[m][3][2*p+1]);
                __half2 si = sig_h2(gi);
                __half2 sf = sig_h2(gf);
                __half2 so = sig_h2(go);
                __half2 tg = tanh_h2(gg);
                __half2 ig = __hmul2(si, tg);
                float2 fig = __half22float2(ig);
                float2 ff  = __half22float2(sf);
                float c0 = fmaf(ff.x, cst[m][2*p],     fig.x);
                float c1 = fmaf(ff.y, cst[m][2*p + 1], fig.y);
                cst[m][2*p]     = c0;
                cst[m][2*p + 1] = c1;
                __half2 tc = tanh_h2(__floats2half2_rn(c0, c1));
                __half2 h2 = __hmul2(so, tc);
                hst[m][p] = *reinterpret_cast<uint32_t*>(&h2);
            }
#pragma unroll
        for (int m = 0; m < 2; m++)
#pragma unroll
            for (int p = 0; p < 2; p++)
                *reinterpret_cast<uint32_t*>(dsm + hwb + sth[m * 2 + p]) = hst[m][p];
    }

    __syncthreads();   // final h (= agg, buffer 1) visible

    // ================= combine epilogue =================
    const uint32_t aggb = 4096;   // (DD-1)&1 == 1
    const uint32_t lmwl = sm32 + (uint32_t)(WLOFF +
                          ((8 * w + l7) * WLPITCH + ((lane >> 3) & 1) * 8) * 2);

    float acc[2][4];
    {
        float b0 = __ldg(&bl[col0]), b1 = __ldg(&bl[col0 + 1]);
#pragma unroll
        for (int m = 0; m < 2; m++) {
            acc[m][0] = b0; acc[m][1] = b1; acc[m][2] = b0; acc[m][3] = b1;
        }
    }
#pragma unroll
    for (int kk = 0; kk < KKC; kk++) {
        uint32_t A0[4], A1[4];
        if (kk < KKX) {
            int rr0 = l7 + (sub & 1) * 8;
            int gcol = kk * 2 + (sub >> 1);
            uint32_t a0 = sm32 + (uint32_t)(XSOFF + rr0 * (XPITCH * 2) + gcol * 16);
            uint32_t a1 = a0 + (uint32_t)(16 * XPITCH * 2);
            LDM4(A0, a0);
            LDM4(A1, a1);
        } else {
            LDM4(A0, lmh[0][kk - KKX] + aggb);
            LDM4(A1, lmh[1][kk - KKX] + aggb);
        }
        uint32_t B0, B1;
        LDM2(B0, B1, lmwl + (uint32_t)(kk * 16 * 2));
        MMA(acc[0], A0, B0, B1);
        MMA(acc[1], A1, B0, B1);
    }
#pragma unroll
    for (int m = 0; m < 2; m++)
#pragma unroll
        for (int e = 0; e < 4; e++)
            acc[m][e] = fmaxf(acc[m][e], 0.0f);

    if constexpr (LAST) {
        // out[n] = comb[n] . Wo + bo (partials in dead x-stage region)
        float wo0 = __ldg(&Wo[col0]), wo1 = __ldg(&Wo[col0 + 1]);
        float* part = reinterpret_cast<float*>(dsm);
#pragma unroll
        for (int m = 0; m < 2; m++)
#pragma unroll
            for (int rh = 0; rh < 2; rh++) {
                int r = m * 16 + rh * 8 + grp;
                part[r * 33 + w * 4 + tig] =
                    acc[m][rh * 2] * wo0 + acc[m][rh * 2 + 1] * wo1;
            }
        __syncthreads();
        if (tid < MT) {
            float s = 0.0f;
#pragma unroll
            for (int j = 0; j < 32; j++) s += part[tid * 33 + j];
            outp[base + tid] = s + __ldg(&bo[0]);
        }
    } else {
        // comb -> h16out (next layer gather + combine source)
#pragma unroll
        for (int m = 0; m < 2; m++)
#pragma unroll
            for (int rh = 0; rh < 2; rh++) {
                int r = m * 16 + rh * 8 + grp;
                uint32_t v = pack2(acc[m][rh * 2], acc[m][rh * 2 + 1]);
                *reinterpret_cast<uint32_t*>(
                    &h16out[(size_t)(base + r) * HH + col0]) = v;
            }
    }
}

// ---------------- launch ----------------
extern "C" void kernel_launch(void* const* d_in, const int* in_sizes, int n_in,
                              void* d_out, int out_size) {
    const float* node_features = (const float*)d_in[0];
    const int*   nbr           = (const int*)d_in[1];
    const float* W_ih[3] = {(const float*)d_in[2],  (const float*)d_in[8],  (const float*)d_in[14]};
    const float* W_hh[3] = {(const float*)d_in[3],  (const float*)d_in[9],  (const float*)d_in[15]};
    const float* b_ih[3] = {(const float*)d_in[4],  (const float*)d_in[10], (const float*)d_in[16]};
    const float* b_hh[3] = {(const float*)d_in[5],  (const float*)d_in[11], (const float*)d_in[17]};
    const float* Wl[3]   = {(const float*)d_in[6],  (const float*)d_in[12], (const float*)d_in[18]};
    const float* bl[3]   = {(const float*)d_in[7],  (const float*)d_in[13], (const float*)d_in[19]};
    const float* W_out   = (const float*)d_in[20];
    const float* b_out   = (const float*)d_in[21];
    float* out = (float*)d_out;

    void *pX0, *pA, *pB;
    cudaGetSymbolAddress(&pX0, g_x0);
    cudaGetSymbolAddress(&pA, g_h16a);
    cudaGetSymbolAddress(&pB, g_h16b);
    __half* x0  = (__half*)pX0;
    __half* hA  = (__half*)pA;
    __half* hB  = (__half*)pB;

    // smem totals (must match kernel constexpr math)
    // L0 (XK=16): 2*1024 + 8192 + 256*24*2 + 64*88*2 + 32*24*2 + 4096 = 39424
    // L12(XK=64): 2*4096 + 8192 + 256*72*2 + 64*136*2 + 32*72*2 + 4096 = 79360
    constexpr int SM_L0  = 39424;
    constexpr int SM_L12 = 79360;
    cudaFuncSetAttribute((const void*)lstm_fused_kernel<16,3,false>,
                         cudaFuncAttributeMaxDynamicSharedMemorySize, SM_L0);
    cudaFuncSetAttribute((const void*)lstm_fused_kernel<64,64,false>,
                         cudaFuncAttributeMaxDynamicSharedMemorySize, SM_L12);
    cudaFuncSetAttribute((const void*)lstm_fused_kernel<64,64,true>,
                         cudaFuncAttributeMaxDynamicSharedMemorySize, SM_L12);

    sort_nbr_kernel<<<(NN * 32 + 255) / 256, 256>>>(nbr);
    prep_x0_kernel<<<(NN * 16 + 255) / 256, 256>>>(node_features);

    // layer 0: gathers x0, combine-x = node_features -> hA
    lstm_fused_kernel<16,3,false><<<NBLK_LSTM, 256, SM_L0>>>(
        W_hh[0], W_ih[0], b_ih[0], b_hh[0], x0, nullptr, node_features,
        Wl[0], bl[0], nullptr, nullptr, hA, nullptr);

    // layer 1: gathers hA, combine-x = hA -> hB
    lstm_fused_kernel<64,64,false><<<NBLK_LSTM, 256, SM_L12>>>(
        W_hh[1], W_ih[1], b_ih[1], b_hh[1], hA, hA, nullptr,
        Wl[1], bl[1], nullptr, nullptr, hB, nullptr);

    // layer 2: gathers hB, combine-x = hB -> out
    lstm_fused_kernel<64,64,true><<<NBLK_LSTM, 256, SM_L12>>>(
        W_hh[2], W_ih[2], b_ih[2], b_hh[2], hB, hB, nullptr,
        Wl[2], bl[2], W_out, b_out, nullptr, out);
}

// round 14
// speedup vs baseline: 1.2473x; 1.2473x over previous
#include <cuda_runtime.h>
#include <cuda_fp16.h>
#include <cstdint>

#define NN    20000
#define DD    32
#define HH    64
#define G4    256   // 4*H
#define MT    32    // nodes per lstm block
#define NBLK_LSTM (NN / MT)   // 625
#define XSTG  17056           // one P-stage buffer

// ---------------- scratch ----------------
__device__ int    g_nbr_sorted[NN * DD];
__device__ __half g_P16a[(size_t)NN * G4];   // double-buffered fp16 projections
__device__ __half g_P16b[(size_t)NN * G4];
__device__ __half g_hf16[(size_t)NN * HH];   // fp16 layer outputs (combine-x)

// ---------------- helpers ----------------
__device__ __forceinline__ uint32_t pack2(float a, float b) {
    __half2 h = __floats2half2_rn(a, b);
    return *reinterpret_cast<uint32_t*>(&h);
}
__device__ __forceinline__ uint32_t pack2f(float2 v) {
    __half2 h = __floats2half2_rn(v.x, v.y);
    return *reinterpret_cast<uint32_t*>(&h);
}
__device__ __forceinline__ __half2 tanh_h2(__half2 x) {
    uint32_t xi = *reinterpret_cast<uint32_t*>(&x);
    uint32_t yi;
    asm("tanh.approx.f16x2 %0, %1;" : "=r"(yi) : "r"(xi));
    return *reinterpret_cast<__half2*>(&yi);
}
__device__ __forceinline__ __half2 sig_h2(__half2 x) {
    const __half2 h = __float2half2_rn(0.5f);
    return __hfma2(tanh_h2(__hmul2(x, h)), h, h);
}
__device__ __forceinline__ void cp_async16(uint32_t dst_smem, const void* src) {
    asm volatile("cp.async.ca.shared.global [%0], [%1], 16;" :: "r"(dst_smem), "l"(src));
}

// ---------------- 1) sort neighbors ----------------
__global__ void sort_nbr_kernel(const int* __restrict__ nbr) {
    int gtid = blockIdx.x * blockDim.x + threadIdx.x;
    int node = gtid >> 5;
    int lane = gtid & 31;
    if (node >= NN) return;
    int v = nbr[node * DD + lane];
#pragma unroll
    for (int k = 2; k <= 32; k <<= 1) {
#pragma unroll
        for (int j = k >> 1; j > 0; j >>= 1) {
            int p = __shfl_xor_sync(0xffffffffu, v, j);
            bool keepMin = (((lane & j) == 0) == ((lane & k) == 0));
            int mn = min(v, p), mx = max(v, p);
            v = keepMin ? mn : mx;
        }
    }
    g_nbr_sorted[node * DD + lane] = v;
}

// ---------------- 2) layer-0 proj: P16a = x3 @ W_ih^T + b ----------------
__global__ __launch_bounds__(256) void proj16_l0_kernel(const float* __restrict__ src,
                                                        const float* __restrict__ W_ih,
                                                        const float* __restrict__ b_ih,
                                                        const float* __restrict__ b_hh) {
    __shared__ float hrow[16 * 3];
    const int j    = threadIdx.x;
    const int base = blockIdx.x * 16;

    float w0 = __ldg(&W_ih[j * 3 + 0]);
    float w1 = __ldg(&W_ih[j * 3 + 1]);
    float w2 = __ldg(&W_ih[j * 3 + 2]);
    float bias = __ldg(&b_ih[j]) + __ldg(&b_hh[j]);

    for (int e = j; e < 16 * 3; e += 256) hrow[e] = src[(size_t)base * 3 + e];
    __syncthreads();

#pragma unroll
    for (int n = 0; n < 16; n++) {
        float acc = bias;
        acc = fmaf(hrow[n * 3 + 0], w0, acc);
        acc = fmaf(hrow[n * 3 + 1], w1, acc);
        acc = fmaf(hrow[n * 3 + 2], w2, acc);
        g_P16a[(size_t)(base + n) * G4 + j] = __float2half(acc);
    }
}

// ---------------- 3) fused LSTM + combine + next-layer proj (+ out) ----------------
// In-loop: gates = P16in[idx_t] (cp.async-staged) + h@W_hh^T (HMMA K=64).
// f16x2 activations, fp32 cell state.
// Epilogue: comb = relu([x|agg]@Wl^T+bl); NEXT: P16out = comb@Wihn^T + bn;
// LAST: out = comb.Wo + bo via smem reduction.

template <int XP, int XIND, bool NEXT, bool LAST>
__global__ __launch_bounds__(256, 2) void lstm_fused_kernel(
    const float* __restrict__ W_hh,
    const __half* __restrict__ P16in,
    const __half* __restrict__ x16,
    const float*  __restrict__ xf32,
    const float*  __restrict__ Wl,
    const float*  __restrict__ bl,
    const float*  __restrict__ Wihn,   // next layer W_ih [256,64]
    const float*  __restrict__ bihn,
    const float*  __restrict__ bhhn,
    const float*  __restrict__ Wo,
    const float*  __restrict__ bo,
    __half* __restrict__ P16out,
    __half* __restrict__ h16out,
    float* __restrict__ outp)
{
    extern __shared__ char dsm[];
    constexpr int HB0    = 2 * XSTG;
    constexpr int KD2    = XP + 64;
    constexpr int KDT    = XIND + 64;
    constexpr int WPITCH = KD2 + 8;
    constexpr int WLOFF  = HB0 + 8192;
    constexpr int XPITCH = XP + 8;
    constexpr int XSOFF  = WLOFF + 64 * WPITCH * 2;
    constexpr int KKC    = KD2 / 16;
    constexpr int KKXT   = XP / 16;

    const int tid  = threadIdx.x;
    const int w    = tid >> 5;
    const int lane = tid & 31;
    const int grp  = lane >> 2;
    const int tig  = lane & 3;
    const int base = blockIdx.x * MT;
    const int col0 = 8 * w + tig * 2;

    const uint32_t sm32 = (uint32_t)__cvta_generic_to_shared(dsm);

    // ---- W_hh -> B fragments (vectorized float2 loads) ----
    uint32_t Bhh[4][4][2];
#pragma unroll
    for (int g = 0; g < 4; g++) {
        const float* row = W_hh + (size_t)(64 * g + 8 * w + grp) * HH;
#pragma unroll
        for (int kk = 0; kk < 4; kk++) {
            const float2* rk = reinterpret_cast<const float2*>(row + kk * 16 + tig * 2);
            Bhh[g][kk][0] = pack2f(__ldg(rk));
            Bhh[g][kk][1] = pack2f(__ldg(rk + 4));
        }
    }

    // ---- Wl -> smem fp16 ----
    {
        __half* wsm = reinterpret_cast<__half*>(dsm + WLOFF);
        for (int e = tid; e < 64 * KD2; e += 256) {
            int n = e / KD2, k = e - n * KD2;
            float v;
            if (k < XP) v = (k < XIND) ? __ldg(&Wl[n * KDT + k]) : 0.0f;
            else        v = __ldg(&Wl[n * KDT + XIND + (k - XP)]);
            wsm[n * WPITCH + k] = __float2half(v);
        }
    }
    // ---- combine-x -> smem fp16 ----
    {
        __half* xsm = reinterpret_cast<__half*>(dsm + XSOFF);
        for (int e = tid; e < MT * XP; e += 256) {
            int r = e / XP, k = e - r * XP;
            __half v;
            if (XIND == 3) v = __float2half(k < 3 ? __ldg(&xf32[(base + r) * 3 + k]) : 0.0f);
            else           v = x16[(size_t)(base + r) * HH + k];
            xsm[r * XPITCH + k] = v;
        }
    }

    // ---- ldmatrix addrs for h ----
    uint32_t lmh[2][4];
    {
        int sub = lane >> 3;
#pragma unroll
        for (int m = 0; m < 2; m++)
#pragma unroll
            for (int kk = 0; kk < 4; kk++) {
                int rr   = m * 16 + (lane & 7) + (sub & 1) * 8;
                int gcol = kk * 2 + (sub >> 1);
                int pc   = (gcol ^ (rr & 7));
                lmh[m][kk] = sm32 + (uint32_t)(HB0 + rr * 128 + pc * 16);
            }
    }
    uint32_t sth[4];
    {
        int pc = ((w ^ grp) << 3) + tig * 2;
#pragma unroll
        for (int j = 0; j < 4; j++) {
            int r = (j >> 1) * 16 + (j & 1) * 8 + grp;
            sth[j] = (uint32_t)(HB0 + r * 128 + pc * 2);
        }
    }

    const int sr = tid >> 3;
    const int sj = tid & 7;
    const int nbase = (base + sr) * DD;

    for (int e = tid; e < 2 * MT * HH / 2; e += 256)
        reinterpret_cast<uint32_t*>(dsm + HB0)[e] = 0u;

    {
        int idx = __ldg(&g_nbr_sorted[nbase + 0]);
#pragma unroll
        for (int g = 0; g < 4; g++)
            cp_async16(sm32 + (uint32_t)((sr * 33 + g * 8 + sj) * 16),
                       P16in + (size_t)idx * G4 + (g * 8 + sj) * 8);
        asm volatile("cp.async.commit_group;");
    }

    float cst[2][4] = {{0.f,0.f,0.f,0.f},{0.f,0.f,0.f,0.f}};

#pragma unroll 1
    for (int t = 0; t < DD; t++) {
        const int sb  = (t & 1) * XSTG;
        const uint32_t hrb = (uint32_t)(((t & 1) ^ 1) * 4096);
        const uint32_t hwb = (uint32_t)((t & 1) * 4096);

        asm volatile("cp.async.wait_group 0;" ::: "memory");
        __syncthreads();

        if (t < DD - 1) {
            int idx = __ldg(&g_nbr_sorted[nbase + (t + 1)]);
            uint32_t sbn = sm32 + (uint32_t)(((t + 1) & 1) * XSTG);
#pragma unroll
            for (int g = 0; g < 4; g++)
                cp_async16(sbn + (uint32_t)((sr * 33 + g * 8 + sj) * 16),
                           P16in + (size_t)idx * G4 + (g * 8 + sj) * 8);
        }
        asm volatile("cp.async.commit_group;");

        // ---- gate init ----
        float cur[2][4][4];
#pragma unroll
        for (int m = 0; m < 2; m++)
#pragma unroll
            for (int g = 0; g < 4; g++) {
                int r0 = m * 16 + grp;
                const __half2 v0 = *reinterpret_cast<const __half2*>(
                    dsm + sb + (r0 * 33 + g * 8 + w) * 16 + tig * 4);
                const __half2 v1 = *reinterpret_cast<const __half2*>(
                    dsm + sb + ((r0 + 8) * 33 + g * 8 + w) * 16 + tig * 4);
                float2 f0 = __half22float2(v0);
                float2 f1 = __half22float2(v1);
                cur[m][g][0] = f0.x; cur[m][g][1] = f0.y;
                cur[m][g][2] = f1.x; cur[m][g][3] = f1.y;
            }

        // ---- gates += h(t-1) @ W_hh^T ----
#pragma unroll
        for (int kk = 0; kk < 4; kk++) {
            uint32_t A0[4], A1[4];
            asm volatile("ldmatrix.sync.aligned.m8n8.x4.shared.b16 {%0,%1,%2,%3}, [%4];"
                         : "=r"(A0[0]), "=r"(A0[1]), "=r"(A0[2]), "=r"(A0[3])
                         : "r"(lmh[0][kk] + hrb));
            asm volatile("ldmatrix.sync.aligned.m8n8.x4.shared.b16 {%0,%1,%2,%3}, [%4];"
                         : "=r"(A1[0]), "=r"(A1[1]), "=r"(A1[2]), "=r"(A1[3])
                         : "r"(lmh[1][kk] + hrb));
#pragma unroll
            for (int g = 0; g < 4; g++) {
                asm volatile(
                    "mma.sync.aligned.m16n8k16.row.col.f32.f16.f16.f32 "
                    "{%0,%1,%2,%3}, {%4,%5,%6,%7}, {%8,%9}, {%0,%1,%2,%3};"
                    : "+f"(cur[0][g][0]), "+f"(cur[0][g][1]),
                      "+f"(cur[0][g][2]), "+f"(cur[0][g][3])
                    : "r"(A0[0]), "r"(A0[1]), "r"(A0[2]), "r"(A0[3]),
                      "r"(Bhh[g][kk][0]), "r"(Bhh[g][kk][1]));
                asm volatile(
                    "mma.sync.aligned.m16n8k16.row.col.f32.f16.f16.f32 "
                    "{%0,%1,%2,%3}, {%4,%5,%6,%7}, {%8,%9}, {%0,%1,%2,%3};"
                    : "+f"(cur[1][g][0]), "+f"(cur[1][g][1]),
                      "+f"(cur[1][g][2]), "+f"(cur[1][g][3])
                    : "r"(A1[0]), "r"(A1[1]), "r"(A1[2]), "r"(A1[3]),
                      "r"(Bhh[g][kk][0]), "r"(Bhh[g][kk][1]));
            }
        }

        // ---- activations (f16x2) + cell update (fp32 c) ----
        uint32_t hst[2][2];
#pragma unroll
        for (int m = 0; m < 2; m++)
#pragma unroll
            for (int p = 0; p < 2; p++) {
                __half2 gi = __floats2half2_rn(cur[m][0][2*p], cur[m][0][2*p+1]);
                __half2 gf = __floats2half2_rn(cur[m][1][2*p], cur[m][1][2*p+1]);
                __half2 gg = __floats2half2_rn(cur[m][2][2*p], cur[m][2][2*p+1]);
                __half2 go = __floats2half2_rn(cur[m][3][2*p], cur[m][3][2*p+1]);
                __half2 si = sig_h2(gi);
                __half2 sf = sig_h2(gf);
                __half2 so = sig_h2(go);
                __half2 tg = tanh_h2(gg);
                __half2 ig = __hmul2(si, tg);
                float2 fig = __half22float2(ig);
                float2 ff  = __half22float2(sf);
                float c0 = fmaf(ff.x, cst[m][2*p],     fig.x);
                float c1 = fmaf(ff.y, cst[m][2*p + 1], fig.y);
                cst[m][2*p]     = c0;
                cst[m][2*p + 1] = c1;
                __half2 tc = tanh_h2(__floats2half2_rn(c0, c1));
                __half2 h2 = __hmul2(so, tc);
                hst[m][p] = *reinterpret_cast<uint32_t*>(&h2);
            }

#pragma unroll
        for (int m = 0; m < 2; m++)
#pragma unroll
            for (int p = 0; p < 2; p++)
                *reinterpret_cast<uint32_t*>(dsm + hwb + sth[m * 2 + p]) = hst[m][p];
    }

    __syncthreads();   // final h (= agg, buffer 1) visible; buffer 0 dead

    // ================= combine epilogue =================
    const uint32_t aggb = 4096;
    const uint32_t lmw0 = sm32 + (uint32_t)(WLOFF +
                         ((8 * w + (lane & 7)) * WPITCH + ((lane >> 3) & 1) * 8) * 2);

    float acc[2][4];
    {
        float b0 = __ldg(&bl[col0]), b1 = __ldg(&bl[col0 + 1]);
#pragma unroll
        for (int m = 0; m < 2; m++) {
            acc[m][0] = b0; acc[m][1] = b1; acc[m][2] = b0; acc[m][3] = b1;
        }
    }

#pragma unroll
    for (int kk = 0; kk < KKC; kk++) {
        uint32_t A0[4], A1[4];
        if (kk < KKXT) {
            int sub = lane >> 3;
            int rr0 = (lane & 7) + (sub & 1) * 8;
            int gcol = kk * 2 + (sub >> 1);
            uint32_t a0 = sm32 + (uint32_t)(XSOFF + rr0 * (XPITCH * 2) + gcol * 16);
            uint32_t a1 = a0 + (uint32_t)(16 * XPITCH * 2);
            asm volatile("ldmatrix.sync.aligned.m8n8.x4.shared.b16 {%0,%1,%2,%3}, [%4];"
                         : "=r"(A0[0]), "=r"(A0[1]), "=r"(A0[2]), "=r"(A0[3]) : "r"(a0));
            asm volatile("ldmatrix.sync.aligned.m8n8.x4.shared.b16 {%0,%1,%2,%3}, [%4];"
                         : "=r"(A1[0]), "=r"(A1[1]), "=r"(A1[2]), "=r"(A1[3]) : "r"(a1));
        } else {
            asm volatile("ldmatrix.sync.aligned.m8n8.x4.shared.b16 {%0,%1,%2,%3}, [%4];"
                         : "=r"(A0[0]), "=r"(A0[1]), "=r"(A0[2]), "=r"(A0[3])
                         : "r"(lmh[0][kk - KKXT] + aggb));
            asm volatile("ldmatrix.sync.aligned.m8n8.x4.shared.b16 {%0,%1,%2,%3}, [%4];"
                         : "=r"(A1[0]), "=r"(A1[1]), "=r"(A1[2]), "=r"(A1[3])
                         : "r"(lmh[1][kk - KKXT] + aggb));
        }
        uint32_t B0, B1;
        asm volatile("ldmatrix.sync.aligned.m8n8.x2.shared.b16 {%0,%1}, [%2];"
                     : "=r"(B0), "=r"(B1)
                     : "r"(lmw0 + (uint32_t)(kk * 16 * 2)));
        asm volatile(
            "mma.sync.aligned.m16n8k16.row.col.f32.f16.f16.f32 "
            "{%0,%1,%2,%3}, {%4,%5,%6,%7}, {%8,%9}, {%0,%1,%2,%3};"
            : "+f"(acc[0][0]), "+f"(acc[0][1]), "+f"(acc[0][2]), "+f"(acc[0][3])
            : "r"(A0[0]), "r"(A0[1]), "r"(A0[2]), "r"(A0[3]), "r"(B0), "r"(B1));
        asm volatile(
            "mma.sync.aligned.m16n8k16.row.col.f32.f16.f16.f32 "
            "{%0,%1,%2,%3}, {%4,%5,%6,%7}, {%8,%9}, {%0,%1,%2,%3};"
            : "+f"(acc[1][0]), "+f"(acc[1][1]), "+f"(acc[1][2]), "+f"(acc[1][3])
            : "r"(A1[0]), "r"(A1[1]), "r"(A1[2]), "r"(A1[3]), "r"(B0), "r"(B1));
    }

#pragma unroll
    for (int m = 0; m < 2; m++)
#pragma unroll
        for (int e = 0; e < 4; e++)
            acc[m][e] = fmaxf(acc[m][e], 0.0f);

    if constexpr (LAST) {
        float wo0 = __ldg(&Wo[col0]), wo1 = __ldg(&Wo[col0 + 1]);
        float* part = reinterpret_cast<float*>(dsm);
#pragma unroll
        for (int m = 0; m < 2; m++)
#pragma unroll
            for (int rh = 0; rh < 2; rh++) {
                int r = m * 16 + rh * 8 + grp;
                part[r * 33 + w * 4 + tig] =
                    acc[m][rh * 2] * wo0 + acc[m][rh * 2 + 1] * wo1;
            }
        __syncthreads();
        if (tid < MT) {
            float s = 0.0f;
#pragma unroll
            for (int j = 0; j < 32; j++) s += part[tid * 33 + j];
            outp[base + tid] = s + __ldg(&bo[0]);
        }
    }

    if constexpr (NEXT) {
        // ---- comb -> h16out + smem buffer 0 ----
#pragma unroll
        for (int m = 0; m < 2; m++)
#pragma unroll
            for (int p = 0; p < 2; p++) {
                uint32_t v = pack2(acc[m][2 * p], acc[m][2 * p + 1]);
                *reinterpret_cast<uint32_t*>(dsm + sth[m * 2 + p]) = v;
                int r = m * 16 + p * 8 + grp;
                *reinterpret_cast<uint32_t*>(
                    &h16out[(size_t)(base + r) * HH + col0]) = v;
            }

        // ---- W_ih_next -> B fragments (float2 loads) ----
        uint32_t Bih[4][4][2];
#pragma unroll
        for (int g = 0; g < 4; g++) {
            const float* row = Wihn + (size_t)(64 * g + 8 * w + grp) * HH;
#pragma unroll
            for (int kk = 0; kk < 4; kk++) {
                const float2* rk = reinterpret_cast<const float2*>(row + kk * 16 + tig * 2);
                Bih[g][kk][0] = pack2f(__ldg(rk));
                Bih[g][kk][1] = pack2f(__ldg(rk + 4));
            }
        }
        float bn[4][2];
#pragma unroll
        for (int g = 0; g < 4; g++) {
#pragma unroll
            for (int e = 0; e < 2; e++) {
                int c = 64 * g + col0 + e;
                bn[g][e] = __ldg(&bihn[c]) + __ldg(&bhhn[c]);
            }
        }
        __syncthreads();   // comb stores visible

        float pc[2][4][4];
#pragma unroll
        for (int m = 0; m < 2; m++)
#pragma unroll
            for (int g = 0; g < 4; g++) {
                pc[m][g][0] = bn[g][0]; pc[m][g][1] = bn[g][1];
                pc[m][g][2] = bn[g][0]; pc[m][g][3] = bn[g][1];
            }
#pragma unroll
        for (int kk = 0; kk < 4; kk++) {
            uint32_t A0[4], A1[4];
            asm volatile("ldmatrix.sync.aligned.m8n8.x4.shared.b16 {%0,%1,%2,%3}, [%4];"
                         : "=r"(A0[0]), "=r"(A0[1]), "=r"(A0[2]), "=r"(A0[3])
                         : "r"(lmh[0][kk]));
            asm volatile("ldmatrix.sync.aligned.m8n8.x4.shared.b16 {%0,%1,%2,%3}, [%4];"
                         : "=r"(A1[0]), "=r"(A1[1]), "=r"(A1[2]), "=r"(A1[3])
                         : "r"(lmh[1][kk]));
#pragma unroll
            for (int g = 0; g < 4; g++) {
                asm volatile(
                    "mma.sync.aligned.m16n8k16.row.col.f32.f16.f16.f32 "
                    "{%0,%1,%2,%3}, {%4,%5,%6,%7}, {%8,%9}, {%0,%1,%2,%3};"
                    : "+f"(pc[0][g][0]), "+f"(pc[0][g][1]),
                      "+f"(pc[0][g][2]), "+f"(pc[0][g][3])
                    : "r"(A0[0]), "r"(A0[1]), "r"(A0[2]), "r"(A0[3]),
                      "r"(Bih[g][kk][0]), "r"(Bih[g][kk][1]));
                asm volatile(
                    "mma.sync.aligned.m16n8k16.row.col.f32.f16.f16.f32 "
                    "{%0,%1,%2,%3}, {%4,%5,%6,%7}, {%8,%9}, {%0,%1,%2,%3};"
                    : "+f"(pc[1][g][0]), "+f"(pc[1][g][1]),
                      "+f"(pc[1][g][2]), "+f"(pc[1][g][3])
                    : "r"(A1[0]), "r"(A1[1]), "r"(A1[2]), "r"(A1[3]),
                      "r"(Bih[g][kk][0]), "r"(Bih[g][kk][1]));
            }
        }

#pragma unroll
        for (int m = 0; m < 2; m++)
#pragma unroll
            for (int rh = 0; rh < 2; rh++) {
                int r = m * 16 + rh * 8 + grp;
#pragma unroll
                for (int g = 0; g < 4; g++) {
                    __half2 h2 = __floats2half2_rn(pc[m][g][rh * 2], pc[m][g][rh * 2 + 1]);
                    *reinterpret_cast<__half2*>(
                        &P16out[(size_t)(base + r) * G4 + 64 * g + col0]) = h2;
                }
            }
    }
}

// ---------------- launch ----------------
extern "C" void kernel_launch(void* const* d_in, const int* in_sizes, int n_in,
                              void* d_out, int out_size) {
    const float* node_features = (const float*)d_in[0];
    const int*   nbr           = (const int*)d_in[1];
    const float* W_ih[3] = {(const float*)d_in[2],  (const float*)d_in[8],  (const float*)d_in[14]};
    const float* W_hh[3] = {(const float*)d_in[3],  (const float*)d_in[9],  (const float*)d_in[15]};
    const float* b_ih[3] = {(const float*)d_in[4],  (const float*)d_in[10], (const float*)d_in[16]};
    const float* b_hh[3] = {(const float*)d_in[5],  (const float*)d_in[11], (const float*)d_in[17]};
    const float* Wl[3]   = {(const float*)d_in[6],  (const float*)d_in[12], (const float*)d_in[18]};
    const float* bl[3]   = {(const float*)d_in[7],  (const float*)d_in[13], (const float*)d_in[19]};
    const float* W_out   = (const float*)d_in[20];
    const float* b_out   = (const float*)d_in[21];
    float* out = (float*)d_out;

    void *pPa, *pPb, *pH16;
    cudaGetSymbolAddress(&pPa, g_P16a);
    cudaGetSymbolAddress(&pPb, g_P16b);
    cudaGetSymbolAddress(&pH16, g_hf16);
    __half* Pa  = (__half*)pPa;
    __half* Pb  = (__half*)pPb;
    __half* h16 = (__half*)pH16;

    constexpr int SM_L0 = 2*XSTG + 8192 + 64*(16+64+8)*2 + 32*(16+8)*2;   // 55104
    constexpr int SM_L12= 2*XSTG + 8192 + 64*(64+64+8)*2 + 32*(64+8)*2;   // 64320
    cudaFuncSetAttribute((const void*)lstm_fused_kernel<16,3,true,false>,
                         cudaFuncAttributeMaxDynamicSharedMemorySize, SM_L0);
    cudaFuncSetAttribute((const void*)lstm_fused_kernel<64,64,true,false>,
                         cudaFuncAttributeMaxDynamicSharedMemorySize, SM_L12);
    cudaFuncSetAttribute((const void*)lstm_fused_kernel<64,64,false,true>,
                         cudaFuncAttributeMaxDynamicSharedMemorySize, SM_L12);

    const int NBLK16 = NN / 16;  // 1250

    sort_nbr_kernel<<<(NN * 32 + 255) / 256, 256>>>(nbr);
    proj16_l0_kernel<<<NBLK16, 256>>>(node_features, W_ih[0], b_ih[0], b_hh[0]);

    // layer 0: reads Pa; epilogue writes h16 + Pb (for layer 1)
    lstm_fused_kernel<16,3,true,false><<<NBLK_LSTM, 256, SM_L0>>>(
        W_hh[0], Pa, nullptr, node_features, Wl[0], bl[0],
        W_ih[1], b_ih[1], b_hh[1], nullptr, nullptr, Pb, h16, nullptr);

    // layer 1: reads Pb + h16; epilogue writes h16 + Pa (for layer 2)
    lstm_fused_kernel<64,64,true,false><<<NBLK_LSTM, 256, SM_L12>>>(
        W_hh[1], Pb, h16, nullptr, Wl[1], bl[1],
        W_ih[2], b_ih[2], b_hh[2], nullptr, nullptr, Pa, h16, nullptr);

    // layer 2: reads Pa + h16; epilogue reduces out
    lstm_fused_kernel<64,64,false,true><<<NBLK_LSTM, 256, SM_L12>>>(
        W_hh[2], Pa, h16, nullptr, Wl[2], bl[2],
        nullptr, nullptr, nullptr, W_out, b_out, nullptr, nullptr, out);
}